// round 15
// baseline (speedup 1.0000x reference)
#include <cuda_runtime.h>
#include <cstdint>

#define B_  8
#define C_  19
#define H_  512
#define W_  512
#define PLANE (H_*W_)          // 262144
#define BC (B_*C_)             // 152

#define SEG 216                // per-batch segment: 64 argmax + 152 modulate
#define NCTA (SEG * B_)        // 1728

__device__ float g_adjusted[BC * 4096];
__device__ int   g_done[B_];
__device__ int   g_mpass[B_];

// exact bf16 pack of two f32 (values are k/64 -> exactly representable)
__device__ __forceinline__ uint32_t packbf(float a, float b) {
    return (__float_as_uint(a) >> 16) | (__float_as_uint(b) & 0xFFFF0000u);
}
// exact unpack, volatile asm so it cannot be hoisted out of the tile loop
#define UNPK(w, lo, hi) do {                                        \
    uint32_t _ul, _uh;                                              \
    asm volatile("shl.b32 %0, %1, 16;"        : "=r"(_ul) : "r"(w));\
    asm volatile("and.b32 %0, %1, 0xFFFF0000;": "=r"(_uh) : "r"(w));\
    lo = __uint_as_float(_ul); hi = __uint_as_float(_uh);           \
} while (0)

// ---------------------------------------------------------------------------
// Argmax role: CTA = one 8-row strip of batch b, 256 threads.
// DEFAULT-policy loads: x[b] (19.9 MB) stays L2-resident for M(b).
// ---------------------------------------------------------------------------
__device__ __forceinline__ void argmax_role(const float* __restrict__ x,
                                            int b, int strip, char* smem_raw)
{
    int (*hist)[20] = (int(*)[20])smem_raw;
    const int t  = threadIdx.x;
    const int cq = t & 127;
    const int rh = t >> 7;

    for (int i = t; i < 64 * 20; i += 256) ((int*)hist)[i] = 0;
    __syncthreads();

    const float* xb = x + (size_t)b * C_ * PLANE
                        + ((size_t)strip * 8 + rh * 4) * W_ + cq * 4;
    const int blk = cq >> 1;

    #pragma unroll
    for (int r = 0; r < 4; r++) {
        const float* row = xb + r * W_;
        float4 bv = *(const float4*)row;
        int bx = 0, by = 0, bz = 0, bw = 0;
        #pragma unroll
        for (int c = 1; c < C_; c++) {
            float4 v = *(const float4*)(row + (size_t)c * PLANE);
            if (v.x > bv.x) { bv.x = v.x; bx = c; }
            if (v.y > bv.y) { bv.y = v.y; by = c; }
            if (v.z > bv.z) { bv.z = v.z; bz = c; }
            if (v.w > bv.w) { bv.w = v.w; bw = c; }
        }
        atomicAdd(&hist[blk][bx], 1);
        atomicAdd(&hist[blk][by], 1);
        atomicAdd(&hist[blk][bz], 1);
        atomicAdd(&hist[blk][bw], 1);
    }
    __syncthreads();

    for (int i = t; i < 64 * C_; i += 256) {
        int j = i / C_, c = i % C_;
        g_adjusted[((size_t)(b * C_ + c) * 64 + strip) * 64 + j] =
            (float)hist[j][c] * (1.0f / 64.0f);
    }

    __threadfence();
    __syncthreads();
    if (t == 0) atomicAdd(&g_done[b], 1);
}

// ---------------------------------------------------------------------------
// Modulate role: pr packed as 32x uint32 (bf16x2, exact), unpacked per use.
// x via __ldcg (L2 hits on x[b]), outputs __stcs.
// ---------------------------------------------------------------------------
__device__ __forceinline__ void modulate_role(const float* __restrict__ x,
                                              const float* __restrict__ attn,
                                              float* __restrict__ out_y,
                                              float* __restrict__ out_c,
                                              int b, int w, char* smem_raw)
{
    float4* sm_attn = (float4*)smem_raw;       // 128 tiles x 16 floats = 8KB
    const int bc   = b * C_ + (w >> 3);
    const int q    = w & 7;
    const int tid  = threadIdx.x;
    const int mgrp = tid >> 6;
    const int quad = tid & 63;
    const int py   = quad >> 2;
    const int px0  = (quad & 3) << 2;

    // stage attn rows while the dependency may still be pending
    const float4* src = (const float4*)(attn + (size_t)bc * 1024 * 16) + q * 128 * 4;
    for (int i = tid; i < 128 * 4; i += 256) sm_attn[i] = src[i];

    // acquire; last M(b) passer resets counters for the next graph replay
    if (tid == 0) {
        while (((volatile int*)g_done)[b] < 64) __nanosleep(32);
        __threadfence();
        int p = atomicAdd(&g_mpass[b], 1);
        if (p == 151) {
            g_done[b]  = 0;
            g_mpass[b] = 0;
            __threadfence();
        }
    }
    __syncthreads();

    // pr: 16 patch float4s packed into 32 words (exact bf16)
    const float* adjc = g_adjusted + (size_t)bc * 4096;
    uint32_t prw[32];
    #pragma unroll
    for (int pi = 0; pi < 4; pi++)
        #pragma unroll
        for (int pj = 0; pj < 4; pj++) {
            float4 v = __ldcg((const float4*)(adjc + (pi * 16 + py) * 64 + pj * 16 + px0));
            prw[(pi * 4 + pj) * 2 + 0] = packbf(v.x, v.y);
            prw[(pi * 4 + pj) * 2 + 1] = packbf(v.z, v.w);
        }

    const float* xp = x + (size_t)bc * PLANE;
    float*       yp = out_y + (size_t)bc * PLANE;
    float*       cp = out_c + (size_t)bc * PLANE;

    const int mh = q * 4 + mgrp;
    const int h  = mh * 16 + py;
    const size_t base = (size_t)h * W_ + px0;
    const int mlbase = mgrp * 32;

    #pragma unroll 1
    for (int ib = 0; ib < 32; ib += 4) {
        const size_t pix0 = base + (size_t)ib * 16;

        // 4 front-batched loads (MLP_p1 = 4)
        float4 xq0 = __ldcg((const float4*)(xp + pix0));
        float4 xq1 = __ldcg((const float4*)(xp + pix0 + 16));
        float4 xq2 = __ldcg((const float4*)(xp + pix0 + 32));
        float4 xq3 = __ldcg((const float4*)(xp + pix0 + 48));

        #pragma unroll
        for (int j = 0; j < 4; j++) {
            const float4 cur = (j == 0) ? xq0 : (j == 1) ? xq1 : (j == 2) ? xq2 : xq3;
            const size_t pix = pix0 + (size_t)j * 16;
            const int mloc = mlbase + ib + j;

            float4 c4 = make_float4(0.f, 0.f, 0.f, 0.f);
            #pragma unroll
            for (int g = 0; g < 4; g++) {
                float4 a4 = sm_attn[mloc * 4 + g];
                #pragma unroll
                for (int pj = 0; pj < 4; pj++) {
                    const float av = (pj == 0) ? a4.x : (pj == 1) ? a4.y
                                   : (pj == 2) ? a4.z : a4.w;
                    float p0, p1, p2, p3;
                    UNPK(prw[(g * 4 + pj) * 2 + 0], p0, p1);
                    UNPK(prw[(g * 4 + pj) * 2 + 1], p2, p3);
                    c4.x = fmaf(av, p0, c4.x);
                    c4.y = fmaf(av, p1, c4.y);
                    c4.z = fmaf(av, p2, c4.z);
                    c4.w = fmaf(av, p3, c4.w);
                }
            }

            float4 y2;
            float tx = 1.f + c4.x; y2.x = cur.x * tx * tx;
            float ty = 1.f + c4.y; y2.y = cur.y * ty * ty;
            float tz = 1.f + c4.z; y2.z = cur.z * tz * tz;
            float tw = 1.f + c4.w; y2.w = cur.w * tw * tw;

            __stcs((float4*)(yp + pix), y2);
            __stcs((float4*)(cp + pix), c4);
        }
    }
}

// ---------------------------------------------------------------------------
// One launch, per-batch interleaved segments: [A(b):64][M(b):152] x 8.
// 3 CTAs/SM (85-reg cap) for 24 warps of memory concurrency.
// ---------------------------------------------------------------------------
__global__ __launch_bounds__(256, 3) void fused_kernel(
    const float* __restrict__ x,
    const float* __restrict__ attn,
    float* __restrict__ out_y,
    float* __restrict__ out_c)
{
    __shared__ __align__(16) char smem_raw[8192];

    const int b = blockIdx.x / SEG;
    const int u = blockIdx.x - b * SEG;

    if (u < 64)
        argmax_role(x, b, u, smem_raw);
    else
        modulate_role(x, attn, out_y, out_c, b, u - 64, smem_raw);
}

extern "C" void kernel_launch(void* const* d_in, const int* in_sizes, int n_in,
                              void* d_out, int out_size)
{
    const float* x    = (const float*)d_in[0];
    const float* attn = (const float*)d_in[1];
    float* out_y = (float*)d_out;
    float* out_c = (float*)d_out + (size_t)BC * PLANE;

    fused_kernel<<<NCTA, 256>>>(x, attn, out_y, out_c);
}

// round 16
// speedup vs baseline: 1.5687x; 1.5687x over previous
#include <cuda_runtime.h>
#include <cstdint>

#define B_  8
#define C_  19
#define H_  512
#define W_  512
#define PLANE (H_*W_)          // 262144
#define BC (B_*C_)             // 152

#define NCTA 1728              // 64 + 7*216 + 152

__device__ float g_adjusted[BC * 4096];
__device__ int   g_done[B_];
__device__ int   g_mpass[B_];

// ---------------------------------------------------------------------------
// Argmax role (R14): CTA = one 8-row strip of batch b, 256 threads.
// DEFAULT-policy loads: x[b] (19.9 MB) stays L2-resident for M(b).
// ---------------------------------------------------------------------------
__device__ __forceinline__ void argmax_role(const float* __restrict__ x,
                                            int b, int strip, char* smem_raw)
{
    int (*hist)[20] = (int(*)[20])smem_raw;
    const int t  = threadIdx.x;
    const int cq = t & 127;
    const int rh = t >> 7;

    for (int i = t; i < 64 * 20; i += 256) ((int*)hist)[i] = 0;
    __syncthreads();

    const float* xb = x + (size_t)b * C_ * PLANE
                        + ((size_t)strip * 8 + rh * 4) * W_ + cq * 4;
    const int blk = cq >> 1;

    #pragma unroll
    for (int r = 0; r < 4; r++) {
        const float* row = xb + r * W_;
        float4 bv = *(const float4*)row;
        int bx = 0, by = 0, bz = 0, bw = 0;
        #pragma unroll
        for (int c = 1; c < C_; c++) {
            float4 v = *(const float4*)(row + (size_t)c * PLANE);
            if (v.x > bv.x) { bv.x = v.x; bx = c; }
            if (v.y > bv.y) { bv.y = v.y; by = c; }
            if (v.z > bv.z) { bv.z = v.z; bz = c; }
            if (v.w > bv.w) { bv.w = v.w; bw = c; }
        }
        atomicAdd(&hist[blk][bx], 1);
        atomicAdd(&hist[blk][by], 1);
        atomicAdd(&hist[blk][bz], 1);
        atomicAdd(&hist[blk][bw], 1);
    }
    __syncthreads();

    for (int i = t; i < 64 * C_; i += 256) {
        int j = i / C_, c = i % C_;
        g_adjusted[((size_t)(b * C_ + c) * 64 + strip) * 64 + j] =
            (float)hist[j][c] * (1.0f / 64.0f);
    }

    __threadfence();
    __syncthreads();
    if (t == 0) atomicAdd(&g_done[b], 1);
}

// ---------------------------------------------------------------------------
// Modulate role (R14): w in [0,152): plane bc = b*19 + (w>>3), q = w&7.
// pr[16] float4 in regs, x via __ldcg (L2 hits on x[b]), outputs __stcs.
// Last of 152 M(b) CTAs resets the batch counters for the next graph replay.
// ---------------------------------------------------------------------------
__device__ __forceinline__ void modulate_role(const float* __restrict__ x,
                                              const float* __restrict__ attn,
                                              float* __restrict__ out_y,
                                              float* __restrict__ out_c,
                                              int b, int w, char* smem_raw)
{
    float4* sm_attn = (float4*)smem_raw;       // 128 tiles x 16 floats = 8KB
    const int bc   = b * C_ + (w >> 3);
    const int q    = w & 7;
    const int tid  = threadIdx.x;
    const int mgrp = tid >> 6;
    const int quad = tid & 63;
    const int py   = quad >> 2;
    const int px0  = (quad & 3) << 2;

    // stage attn rows while the dependency may still be pending
    const float4* src = (const float4*)(attn + (size_t)bc * 1024 * 16) + q * 128 * 4;
    for (int i = tid; i < 128 * 4; i += 256) sm_attn[i] = src[i];

    // acquire (normally already satisfied under the lookahead schedule)
    if (tid == 0) {
        while (((volatile int*)g_done)[b] < 64) __nanosleep(32);
        __threadfence();
        int p = atomicAdd(&g_mpass[b], 1);
        if (p == 151) {
            g_done[b]  = 0;
            g_mpass[b] = 0;
            __threadfence();
        }
    }
    __syncthreads();

    const float* adjc = g_adjusted + (size_t)bc * 4096;
    float4 pr[16];
    #pragma unroll
    for (int pi = 0; pi < 4; pi++)
        #pragma unroll
        for (int pj = 0; pj < 4; pj++)
            pr[pi * 4 + pj] =
                __ldcg((const float4*)(adjc + (pi * 16 + py) * 64 + pj * 16 + px0));

    const float* xp = x + (size_t)bc * PLANE;
    float*       yp = out_y + (size_t)bc * PLANE;
    float*       cp = out_c + (size_t)bc * PLANE;

    const int mh = q * 4 + mgrp;
    const int h  = mh * 16 + py;
    const size_t base = (size_t)h * W_ + px0;
    const int mlbase = mgrp * 32;

    #pragma unroll 1
    for (int ib = 0; ib < 32; ib += 4) {
        const size_t pix0 = base + (size_t)ib * 16;

        // 4 front-batched loads (MLP_p1 = 4), L2-preferring
        float4 xq0 = __ldcg((const float4*)(xp + pix0));
        float4 xq1 = __ldcg((const float4*)(xp + pix0 + 16));
        float4 xq2 = __ldcg((const float4*)(xp + pix0 + 32));
        float4 xq3 = __ldcg((const float4*)(xp + pix0 + 48));

        #pragma unroll
        for (int j = 0; j < 4; j++) {
            const float4 cur = (j == 0) ? xq0 : (j == 1) ? xq1 : (j == 2) ? xq2 : xq3;
            const size_t pix = pix0 + (size_t)j * 16;
            const int mloc = mlbase + ib + j;

            float4 c4 = make_float4(0.f, 0.f, 0.f, 0.f);
            #pragma unroll
            for (int g = 0; g < 4; g++) {
                float4 a4 = sm_attn[mloc * 4 + g];
                c4.x = fmaf(a4.x, pr[g*4+0].x, c4.x);
                c4.y = fmaf(a4.x, pr[g*4+0].y, c4.y);
                c4.z = fmaf(a4.x, pr[g*4+0].z, c4.z);
                c4.w = fmaf(a4.x, pr[g*4+0].w, c4.w);
                c4.x = fmaf(a4.y, pr[g*4+1].x, c4.x);
                c4.y = fmaf(a4.y, pr[g*4+1].y, c4.y);
                c4.z = fmaf(a4.y, pr[g*4+1].z, c4.z);
                c4.w = fmaf(a4.y, pr[g*4+1].w, c4.w);
                c4.x = fmaf(a4.z, pr[g*4+2].x, c4.x);
                c4.y = fmaf(a4.z, pr[g*4+2].y, c4.y);
                c4.z = fmaf(a4.z, pr[g*4+2].z, c4.z);
                c4.w = fmaf(a4.z, pr[g*4+2].w, c4.w);
                c4.x = fmaf(a4.w, pr[g*4+3].x, c4.x);
                c4.y = fmaf(a4.w, pr[g*4+3].y, c4.y);
                c4.z = fmaf(a4.w, pr[g*4+3].z, c4.z);
                c4.w = fmaf(a4.w, pr[g*4+3].w, c4.w);
            }

            float4 y2;
            float tx = 1.f + c4.x; y2.x = cur.x * tx * tx;
            float ty = 1.f + c4.y; y2.y = cur.y * ty * ty;
            float tz = 1.f + c4.z; y2.z = cur.z * tz * tz;
            float tw = 1.f + c4.w; y2.w = cur.w * tw * tw;

            __stcs((float4*)(yp + pix), y2);
            __stcs((float4*)(cp + pix), c4);
        }
    }
}

// ---------------------------------------------------------------------------
// One launch, one-segment LOOKAHEAD schedule (bids ascending):
//   [A0:64] [A1:64|M0:152] [A2|M1] ... [A7|M6] [M7:152]
// M(b) launches a full segment after A(b) -> dependency ~always satisfied.
// ---------------------------------------------------------------------------
__global__ __launch_bounds__(256, 2) void fused_kernel(
    const float* __restrict__ x,
    const float* __restrict__ attn,
    float* __restrict__ out_y,
    float* __restrict__ out_c)
{
    __shared__ __align__(16) char smem_raw[8192];

    const int bid = blockIdx.x;
    if (bid < 64) {
        argmax_role(x, 0, bid, smem_raw);
    } else if (bid < 64 + 7 * 216) {
        const int s = (bid - 64) / 216;
        const int u = (bid - 64) - s * 216;
        if (u < 64)
            argmax_role(x, s + 1, u, smem_raw);
        else
            modulate_role(x, attn, out_y, out_c, s, u - 64, smem_raw);
    } else {
        modulate_role(x, attn, out_y, out_c, 7, bid - (64 + 7 * 216), smem_raw);
    }
}

extern "C" void kernel_launch(void* const* d_in, const int* in_sizes, int n_in,
                              void* d_out, int out_size)
{
    const float* x    = (const float*)d_in[0];
    const float* attn = (const float*)d_in[1];
    float* out_y = (float*)d_out;
    float* out_c = (float*)d_out + (size_t)BC * PLANE;

    fused_kernel<<<NCTA, 256>>>(x, attn, out_y, out_c);
}

// round 17
// speedup vs baseline: 1.5773x; 1.0055x over previous
#include <cuda_runtime.h>
#include <cstdint>

#define B_  8
#define C_  19
#define H_  512
#define W_  512
#define PLANE (H_*W_)          // 262144
#define BC (B_*C_)             // 152

#define NCTA 1728              // 64 + 7*216 + 152

__device__ float g_adjusted[BC * 4096];
__device__ int   g_done[B_];
__device__ int   g_mpass[B_];

// ---------------------------------------------------------------------------
// Argmax role (R14): CTA = one 8-row strip of batch b, 256 threads.
// DEFAULT-policy loads: x[b] (19.9 MB) stays L2-resident for M(b).
// ---------------------------------------------------------------------------
__device__ __forceinline__ void argmax_role(const float* __restrict__ x,
                                            int b, int strip, char* smem_raw)
{
    int (*hist)[20] = (int(*)[20])smem_raw;
    const int t  = threadIdx.x;
    const int cq = t & 127;
    const int rh = t >> 7;

    for (int i = t; i < 64 * 20; i += 256) ((int*)hist)[i] = 0;
    __syncthreads();

    const float* xb = x + (size_t)b * C_ * PLANE
                        + ((size_t)strip * 8 + rh * 4) * W_ + cq * 4;
    const int blk = cq >> 1;

    #pragma unroll
    for (int r = 0; r < 4; r++) {
        const float* row = xb + r * W_;
        float4 bv = *(const float4*)row;
        int bx = 0, by = 0, bz = 0, bw = 0;
        #pragma unroll
        for (int c = 1; c < C_; c++) {
            float4 v = *(const float4*)(row + (size_t)c * PLANE);
            if (v.x > bv.x) { bv.x = v.x; bx = c; }
            if (v.y > bv.y) { bv.y = v.y; by = c; }
            if (v.z > bv.z) { bv.z = v.z; bz = c; }
            if (v.w > bv.w) { bv.w = v.w; bw = c; }
        }
        atomicAdd(&hist[blk][bx], 1);
        atomicAdd(&hist[blk][by], 1);
        atomicAdd(&hist[blk][bz], 1);
        atomicAdd(&hist[blk][bw], 1);
    }
    __syncthreads();

    for (int i = t; i < 64 * C_; i += 256) {
        int j = i / C_, c = i % C_;
        g_adjusted[((size_t)(b * C_ + c) * 64 + strip) * 64 + j] =
            (float)hist[j][c] * (1.0f / 64.0f);
    }

    __threadfence();
    __syncthreads();
    if (t == 0) atomicAdd(&g_done[b], 1);
}

// ---------------------------------------------------------------------------
// Modulate role (R14): w in [0,152): plane bc = b*19 + (w>>3), q = w&7.
// pr[16] float4 in regs, x via __ldcg (L2 hits on x[b]), outputs __stcs.
// Last of 152 M(b) CTAs resets the batch counters for the next graph replay.
// ---------------------------------------------------------------------------
__device__ __forceinline__ void modulate_role(const float* __restrict__ x,
                                              const float* __restrict__ attn,
                                              float* __restrict__ out_y,
                                              float* __restrict__ out_c,
                                              int b, int w, char* smem_raw)
{
    float4* sm_attn = (float4*)smem_raw;       // 128 tiles x 16 floats = 8KB
    const int bc   = b * C_ + (w >> 3);
    const int q    = w & 7;
    const int tid  = threadIdx.x;
    const int mgrp = tid >> 6;
    const int quad = tid & 63;
    const int py   = quad >> 2;
    const int px0  = (quad & 3) << 2;

    // stage attn rows while the dependency may still be pending
    const float4* src = (const float4*)(attn + (size_t)bc * 1024 * 16) + q * 128 * 4;
    for (int i = tid; i < 128 * 4; i += 256) sm_attn[i] = src[i];

    // acquire (short or zero wait under the interleaved schedule)
    if (tid == 0) {
        while (((volatile int*)g_done)[b] < 64) __nanosleep(32);
        __threadfence();
        int p = atomicAdd(&g_mpass[b], 1);
        if (p == 151) {
            g_done[b]  = 0;
            g_mpass[b] = 0;
            __threadfence();
        }
    }
    __syncthreads();

    const float* adjc = g_adjusted + (size_t)bc * 4096;
    float4 pr[16];
    #pragma unroll
    for (int pi = 0; pi < 4; pi++)
        #pragma unroll
        for (int pj = 0; pj < 4; pj++)
            pr[pi * 4 + pj] =
                __ldcg((const float4*)(adjc + (pi * 16 + py) * 64 + pj * 16 + px0));

    const float* xp = x + (size_t)bc * PLANE;
    float*       yp = out_y + (size_t)bc * PLANE;
    float*       cp = out_c + (size_t)bc * PLANE;

    const int mh = q * 4 + mgrp;
    const int h  = mh * 16 + py;
    const size_t base = (size_t)h * W_ + px0;
    const int mlbase = mgrp * 32;

    #pragma unroll 1
    for (int ib = 0; ib < 32; ib += 4) {
        const size_t pix0 = base + (size_t)ib * 16;

        // 4 front-batched loads (MLP_p1 = 4), L2-preferring
        float4 xq0 = __ldcg((const float4*)(xp + pix0));
        float4 xq1 = __ldcg((const float4*)(xp + pix0 + 16));
        float4 xq2 = __ldcg((const float4*)(xp + pix0 + 32));
        float4 xq3 = __ldcg((const float4*)(xp + pix0 + 48));

        #pragma unroll
        for (int j = 0; j < 4; j++) {
            const float4 cur = (j == 0) ? xq0 : (j == 1) ? xq1 : (j == 2) ? xq2 : xq3;
            const size_t pix = pix0 + (size_t)j * 16;
            const int mloc = mlbase + ib + j;

            float4 c4 = make_float4(0.f, 0.f, 0.f, 0.f);
            #pragma unroll
            for (int g = 0; g < 4; g++) {
                float4 a4 = sm_attn[mloc * 4 + g];
                c4.x = fmaf(a4.x, pr[g*4+0].x, c4.x);
                c4.y = fmaf(a4.x, pr[g*4+0].y, c4.y);
                c4.z = fmaf(a4.x, pr[g*4+0].z, c4.z);
                c4.w = fmaf(a4.x, pr[g*4+0].w, c4.w);
                c4.x = fmaf(a4.y, pr[g*4+1].x, c4.x);
                c4.y = fmaf(a4.y, pr[g*4+1].y, c4.y);
                c4.z = fmaf(a4.y, pr[g*4+1].z, c4.z);
                c4.w = fmaf(a4.y, pr[g*4+1].w, c4.w);
                c4.x = fmaf(a4.z, pr[g*4+2].x, c4.x);
                c4.y = fmaf(a4.z, pr[g*4+2].y, c4.y);
                c4.z = fmaf(a4.z, pr[g*4+2].z, c4.z);
                c4.w = fmaf(a4.z, pr[g*4+2].w, c4.w);
                c4.x = fmaf(a4.w, pr[g*4+3].x, c4.x);
                c4.y = fmaf(a4.w, pr[g*4+3].y, c4.y);
                c4.z = fmaf(a4.w, pr[g*4+3].z, c4.z);
                c4.w = fmaf(a4.w, pr[g*4+3].w, c4.w);
            }

            float4 y2;
            float tx = 1.f + c4.x; y2.x = cur.x * tx * tx;
            float ty = 1.f + c4.y; y2.y = cur.y * ty * ty;
            float tz = 1.f + c4.z; y2.z = cur.z * tz * tz;
            float tw = 1.f + c4.w; y2.w = cur.w * tw * tw;

            __stcs((float4*)(yp + pix), y2);
            __stcs((float4*)(cp + pix), c4);
        }
    }
}

// ---------------------------------------------------------------------------
// One launch, FINE-GRAINED lookahead schedule (bids ascending):
//   [A0:64]  then 7 segments s=0..6 of 216 bids interleaving
//   A(s+1) (64 units) with M(s) (152 units) in 8 chunks of [8A | 19M],
//   then [M7:152].
// ---------------------------------------------------------------------------
__global__ __launch_bounds__(256, 2) void fused_kernel(
    const float* __restrict__ x,
    const float* __restrict__ attn,
    float* __restrict__ out_y,
    float* __restrict__ out_c)
{
    __shared__ __align__(16) char smem_raw[8192];

    const int bid = blockIdx.x;
    if (bid < 64) {
        argmax_role(x, 0, bid, smem_raw);
    } else if (bid < 64 + 7 * 216) {
        const int s     = (bid - 64) / 216;
        const int u     = (bid - 64) - s * 216;
        const int chunk = u / 27;
        const int pos   = u - chunk * 27;
        if (pos < 8)
            argmax_role(x, s + 1, chunk * 8 + pos, smem_raw);
        else
            modulate_role(x, attn, out_y, out_c, s, chunk * 19 + (pos - 8), smem_raw);
    } else {
        modulate_role(x, attn, out_y, out_c, 7, bid - (64 + 7 * 216), smem_raw);
    }
}

extern "C" void kernel_launch(void* const* d_in, const int* in_sizes, int n_in,
                              void* d_out, int out_size)
{
    const float* x    = (const float*)d_in[0];
    const float* attn = (const float*)d_in[1];
    float* out_y = (float*)d_out;
    float* out_c = (float*)d_out + (size_t)BC * PLANE;

    fused_kernel<<<NCTA, 256>>>(x, attn, out_y, out_c);
}